// round 1
// baseline (speedup 1.0000x reference)
#include <cuda_runtime.h>
#include <cuda_bf16.h>

// Problem constants (fixed by the dataset: b=2, c=8, h=w=128, P=3, Wn=7)
#define IMG_H 128
#define IMG_W 128
#define NCH 8
#define NB 2

#define TY 8
#define TX 16
#define NTHREADS (TY*TX)
#define HP 4                 // phi halo: window +-3 plus patch +-1
#define HG 3                 // g halo: window +-3
#define PH (TY + 2*HP)       // 16
#define PW (TX + 2*HP)       // 24
#define GH (TY + 2*HG)       // 14
#define GW (TX + 2*HG)       // 22

__global__ __launch_bounds__(NTHREADS)
void attn_fused_kernel(const float* __restrict__ u,
                       const float* __restrict__ pan,
                       const float* __restrict__ Wphi,
                       const float* __restrict__ Wg,
                       float* __restrict__ out)
{
    __shared__ __align__(16) float phi_s[PH*PW*NCH];
    __shared__ __align__(16) float g_s[GH*GW*NCH];
    __shared__ float wphi_s[NCH*NCH];
    __shared__ float wg_s[NCH*NCH];

    const int tid  = threadIdx.x;
    const int bimg = blockIdx.z;
    const int y0   = blockIdx.y * TY;
    const int x0   = blockIdx.x * TX;

    if (tid < NCH*NCH) { wphi_s[tid] = Wphi[tid]; wg_s[tid] = Wg[tid]; }
    __syncthreads();

    const float* panb = pan + (size_t)bimg * NCH * IMG_H * IMG_W;
    const float* ub   = u   + (size_t)bimg * NCH * IMG_H * IMG_W;

    // ---- phi0 tile with +-4 halo: phi0 = W_phi @ pan (zero outside image) ----
    for (int i = tid; i < PH*PW; i += NTHREADS) {
        int r = i / PW, c = i % PW;
        int gy = y0 - HP + r, gx = x0 - HP + c;
        bool in = ((unsigned)gy < IMG_H) && ((unsigned)gx < IMG_W);
        float pv[NCH];
        #pragma unroll
        for (int ch = 0; ch < NCH; ch++)
            pv[ch] = in ? panb[ch*IMG_H*IMG_W + gy*IMG_W + gx] : 0.f;
        #pragma unroll
        for (int o = 0; o < NCH; o++) {
            float acc = 0.f;
            #pragma unroll
            for (int ci = 0; ci < NCH; ci++)
                acc = fmaf(wphi_s[o*NCH+ci], pv[ci], acc);
            phi_s[i*NCH + o] = acc;
        }
    }

    // ---- g tile with +-3 halo: g = W_g @ u (zero outside image) ----
    for (int i = tid; i < GH*GW; i += NTHREADS) {
        int r = i / GW, c = i % GW;
        int gy = y0 - HG + r, gx = x0 - HG + c;
        bool in = ((unsigned)gy < IMG_H) && ((unsigned)gx < IMG_W);
        float uv[NCH];
        #pragma unroll
        for (int ch = 0; ch < NCH; ch++)
            uv[ch] = in ? ub[ch*IMG_H*IMG_W + gy*IMG_W + gx] : 0.f;
        #pragma unroll
        for (int o = 0; o < NCH; o++) {
            float acc = 0.f;
            #pragma unroll
            for (int ci = 0; ci < NCH; ci++)
                acc = fmaf(wg_s[o*NCH+ci], uv[ci], acc);
            g_s[i*NCH + o] = acc;
        }
    }
    __syncthreads();

    const int ty = tid / TX, tx = tid % TX;
    const int gy = y0 + ty, gx = x0 + tx;

    // theta descriptor of this pixel: 3x3 patch x 8 ch, kept in registers
    float4 ta[9], tb[9];
    #pragma unroll
    for (int p = 0; p < 9; p++) {
        int py = p/3 - 1, px = p%3 - 1;
        int idx = ((ty+HP+py)*PW + (tx+HP+px))*NCH;
        ta[p] = *(const float4*)&phi_s[idx];
        tb[p] = *(const float4*)&phi_s[idx+4];
    }

    // online softmax over the 49 window positions, fused with g-weighted sum
    float m = -3.4e38f, ssum = 0.f;
    float o0x=0.f,o0y=0.f,o0z=0.f,o0w=0.f;
    float o1x=0.f,o1y=0.f,o1z=0.f,o1w=0.f;

    for (int j = 0; j < 49; j++) {
        int dy = j/7 - 3, dx = j%7 - 3;

        float dot = 0.f;
        #pragma unroll
        for (int p = 0; p < 9; p++) {
            int py = p/3 - 1, px = p%3 - 1;
            int idx = ((ty+HP+dy+py)*PW + (tx+HP+dx+px))*NCH;
            float4 a  = *(const float4*)&phi_s[idx];
            float4 bq = *(const float4*)&phi_s[idx+4];
            dot = fmaf(ta[p].x, a.x, dot);
            dot = fmaf(ta[p].y, a.y, dot);
            dot = fmaf(ta[p].z, a.z, dot);
            dot = fmaf(ta[p].w, a.w, dot);
            dot = fmaf(tb[p].x, bq.x, dot);
            dot = fmaf(tb[p].y, bq.y, dot);
            dot = fmaf(tb[p].z, bq.z, dot);
            dot = fmaf(tb[p].w, bq.w, dot);
        }

        // double-unfold semantics: whole neighbor descriptor is zero if the
        // window pixel is outside the image -> logit exactly 0 (still in softmax)
        bool in = ((unsigned)(gy+dy) < IMG_H) && ((unsigned)(gx+dx) < IMG_W);
        float l = in ? dot : 0.f;

        float mn = fmaxf(m, l);
        float sc = __expf(m - mn);   // first iter: exp(-huge) -> 0
        float e  = __expf(l - mn);

        int gi = ((ty+HG+dy)*GW + (tx+HG+dx))*NCH;
        float4 gv0 = *(const float4*)&g_s[gi];
        float4 gv1 = *(const float4*)&g_s[gi+4];

        ssum = ssum*sc + e;
        o0x = o0x*sc + e*gv0.x;  o0y = o0y*sc + e*gv0.y;
        o0z = o0z*sc + e*gv0.z;  o0w = o0w*sc + e*gv0.w;
        o1x = o1x*sc + e*gv1.x;  o1y = o1y*sc + e*gv1.y;
        o1z = o1z*sc + e*gv1.z;  o1w = o1w*sc + e*gv1.w;
        m = mn;
    }

    float inv = 1.f / ssum;
    float* ob = out + (size_t)bimg*NCH*IMG_H*IMG_W + (size_t)gy*IMG_W + gx;
    const int PL = IMG_H*IMG_W;
    ob[0*PL] = o0x*inv;  ob[1*PL] = o0y*inv;
    ob[2*PL] = o0z*inv;  ob[3*PL] = o0w*inv;
    ob[4*PL] = o1x*inv;  ob[5*PL] = o1y*inv;
    ob[6*PL] = o1z*inv;  ob[7*PL] = o1w*inv;
}

extern "C" void kernel_launch(void* const* d_in, const int* in_sizes, int n_in,
                              void* d_out, int out_size)
{
    const float* u    = (const float*)d_in[0];
    const float* pan  = (const float*)d_in[1];
    const float* Wphi = (const float*)d_in[2];
    const float* Wg   = (const float*)d_in[3];
    float* out = (float*)d_out;

    dim3 grid(IMG_W / TX, IMG_H / TY, NB);   // (8, 16, 2) = 256 blocks
    dim3 block(NTHREADS);                     // 128
    attn_fused_kernel<<<grid, block>>>(u, pan, Wphi, Wg, out);
}

// round 2
// speedup vs baseline: 1.8210x; 1.8210x over previous
#include <cuda_runtime.h>
#include <cuda_bf16.h>

// Problem constants (fixed by the dataset: b=2, c=8, h=w=128, P=3, Wn=7)
#define IMG_H 128
#define IMG_W 128
#define NCH 8
#define NB 2

#define TY 8
#define TX 16
#define NTHREADS (TY*TX)
#define HP 4                 // phi halo: window +-3 plus patch +-1
#define HG 3                 // g halo: window +-3
#define PH (TY + 2*HP)       // 16
#define PW (TX + 2*HP)       // 24
#define GH (TY + 2*HG)       // 14
#define GW (TX + 2*HG)       // 22

// Correlation map: tile dilated by 1 pixel (patch radius)
#define CW 18                // TX + 2
#define CHh 10               // TY + 2
#define CN (CHh*CW)          // 180

__global__ __launch_bounds__(NTHREADS)
void attn_corr_kernel(const float* __restrict__ u,
                      const float* __restrict__ pan,
                      const float* __restrict__ Wphi,
                      const float* __restrict__ Wg,
                      float* __restrict__ out)
{
    __shared__ __align__(16) float phi_s[PH*PW*NCH];
    __shared__ __align__(16) float g_s[GH*GW*NCH];
    __shared__ float Cs[2*CN];           // double-buffered correlation map
    __shared__ float wphi_s[NCH*NCH];
    __shared__ float wg_s[NCH*NCH];

    const int tid  = threadIdx.x;
    const int bimg = blockIdx.z;
    const int y0   = blockIdx.y * TY;
    const int x0   = blockIdx.x * TX;

    if (tid < NCH*NCH) { wphi_s[tid] = Wphi[tid]; wg_s[tid] = Wg[tid]; }
    __syncthreads();

    const float* panb = pan + (size_t)bimg * NCH * IMG_H * IMG_W;
    const float* ub   = u   + (size_t)bimg * NCH * IMG_H * IMG_W;

    // ---- phi0 tile with +-4 halo: phi0 = W_phi @ pan (zero outside image) ----
    for (int i = tid; i < PH*PW; i += NTHREADS) {
        int r = i / PW, c = i % PW;
        int gy = y0 - HP + r, gx = x0 - HP + c;
        bool in = ((unsigned)gy < IMG_H) && ((unsigned)gx < IMG_W);
        float pv[NCH];
        #pragma unroll
        for (int ch = 0; ch < NCH; ch++)
            pv[ch] = in ? panb[ch*IMG_H*IMG_W + gy*IMG_W + gx] : 0.f;
        #pragma unroll
        for (int o = 0; o < NCH; o++) {
            float acc = 0.f;
            #pragma unroll
            for (int ci = 0; ci < NCH; ci++)
                acc = fmaf(wphi_s[o*NCH+ci], pv[ci], acc);
            phi_s[i*NCH + o] = acc;
        }
    }

    // ---- g tile with +-3 halo: g = W_g @ u (zero outside image) ----
    for (int i = tid; i < GH*GW; i += NTHREADS) {
        int r = i / GW, c = i % GW;
        int gy = y0 - HG + r, gx = x0 - HG + c;
        bool in = ((unsigned)gy < IMG_H) && ((unsigned)gx < IMG_W);
        float uv[NCH];
        #pragma unroll
        for (int ch = 0; ch < NCH; ch++)
            uv[ch] = in ? ub[ch*IMG_H*IMG_W + gy*IMG_W + gx] : 0.f;
        #pragma unroll
        for (int o = 0; o < NCH; o++) {
            float acc = 0.f;
            #pragma unroll
            for (int ci = 0; ci < NCH; ci++)
                acc = fmaf(wg_s[o*NCH+ci], uv[ci], acc);
            g_s[i*NCH + o] = acc;
        }
    }
    __syncthreads();

    const int ty = tid / TX, tx = tid % TX;
    const int gy = y0 + ty, gx = x0 + tx;

    // ---- cache v(a) for this thread's correlation positions in registers ----
    // position p covers pixel (y0-1 + p/CW, x0-1 + p%CW); phi_s cell offset +3
    const int p0   = tid;                     // 0..127
    const int r0   = p0 / CW, c0 = p0 % CW;
    const int cell0 = (r0 + 3) * PW + (c0 + 3);
    float4 v0a = *(const float4*)&phi_s[cell0*NCH];
    float4 v0b = *(const float4*)&phi_s[cell0*NCH + 4];

    const bool has1 = (tid < CN - NTHREADS);  // tid < 52
    const int p1   = tid + NTHREADS;
    const int r1   = p1 / CW, c1 = p1 % CW;
    const int cell1 = (r1 + 3) * PW + (c1 + 3);
    float4 v1a = make_float4(0,0,0,0), v1b = make_float4(0,0,0,0);
    if (has1) {
        v1a = *(const float4*)&phi_s[cell1*NCH];
        v1b = *(const float4*)&phi_s[cell1*NCH + 4];
    }

    // ---- online softmax over 49 window offsets, logits via box-sum of C ----
    float m = -3.4e38f, ssum = 0.f;
    float o0x=0.f,o0y=0.f,o0z=0.f,o0w=0.f;
    float o1x=0.f,o1y=0.f,o1z=0.f,o1w=0.f;

    for (int dy = -3; dy <= 3; dy++) {
        const bool in_y = ((unsigned)(gy + dy) < IMG_H);
        #pragma unroll
        for (int dx = -3; dx <= 3; dx++) {
            const int j = (dy + 3) * 7 + (dx + 3);
            float* Cb = Cs + (j & 1) * CN;
            const int off = (dy * PW + dx) * NCH;

            // C_delta(a) = v(a) . v(a+delta)
            {
                const float4* q = (const float4*)&phi_s[cell0*NCH + off];
                float4 wa = q[0], wb = q[1];
                float cv = v0a.x*wa.x;
                cv = fmaf(v0a.y, wa.y, cv); cv = fmaf(v0a.z, wa.z, cv);
                cv = fmaf(v0a.w, wa.w, cv); cv = fmaf(v0b.x, wb.x, cv);
                cv = fmaf(v0b.y, wb.y, cv); cv = fmaf(v0b.z, wb.z, cv);
                cv = fmaf(v0b.w, wb.w, cv);
                Cb[p0] = cv;
            }
            if (has1) {
                const float4* q = (const float4*)&phi_s[cell1*NCH + off];
                float4 wa = q[0], wb = q[1];
                float cv = v1a.x*wa.x;
                cv = fmaf(v1a.y, wa.y, cv); cv = fmaf(v1a.z, wa.z, cv);
                cv = fmaf(v1a.w, wa.w, cv); cv = fmaf(v1b.x, wb.x, cv);
                cv = fmaf(v1b.y, wb.y, cv); cv = fmaf(v1b.z, wb.z, cv);
                cv = fmaf(v1b.w, wb.w, cv);
                Cb[p1] = cv;
            }
            __syncthreads();

            // logit = 3x3 box-sum of C_delta around this pixel
            const float* row0 = Cb + (ty + 0) * CW + tx;
            const float* row1 = Cb + (ty + 1) * CW + tx;
            const float* row2 = Cb + (ty + 2) * CW + tx;
            float l = row0[0] + row0[1] + row0[2]
                    + row1[0] + row1[1] + row1[2]
                    + row2[0] + row2[1] + row2[2];

            // double-unfold semantics: logit exactly 0 for out-of-image window px
            const bool in = in_y && ((unsigned)(gx + dx) < IMG_W);
            l = in ? l : 0.f;

            float mn = fmaxf(m, l);
            float sc = __expf(m - mn);
            float e  = __expf(l - mn);

            const int gi = ((ty + HG + dy) * GW + (tx + HG + dx)) * NCH;
            float4 gv0 = *(const float4*)&g_s[gi];
            float4 gv1 = *(const float4*)&g_s[gi + 4];

            ssum = ssum*sc + e;
            o0x = o0x*sc + e*gv0.x;  o0y = o0y*sc + e*gv0.y;
            o0z = o0z*sc + e*gv0.z;  o0w = o0w*sc + e*gv0.w;
            o1x = o1x*sc + e*gv1.x;  o1y = o1y*sc + e*gv1.y;
            o1z = o1z*sc + e*gv1.z;  o1w = o1w*sc + e*gv1.w;
            m = mn;
        }
    }

    float inv = 1.f / ssum;
    float* ob = out + (size_t)bimg*NCH*IMG_H*IMG_W + (size_t)gy*IMG_W + gx;
    const int PL = IMG_H*IMG_W;
    ob[0*PL] = o0x*inv;  ob[1*PL] = o0y*inv;
    ob[2*PL] = o0z*inv;  ob[3*PL] = o0w*inv;
    ob[4*PL] = o1x*inv;  ob[5*PL] = o1y*inv;
    ob[6*PL] = o1z*inv;  ob[7*PL] = o1w*inv;
}

extern "C" void kernel_launch(void* const* d_in, const int* in_sizes, int n_in,
                              void* d_out, int out_size)
{
    const float* u    = (const float*)d_in[0];
    const float* pan  = (const float*)d_in[1];
    const float* Wphi = (const float*)d_in[2];
    const float* Wg   = (const float*)d_in[3];
    float* out = (float*)d_out;

    dim3 grid(IMG_W / TX, IMG_H / TY, NB);   // (8, 16, 2) = 256 blocks
    dim3 block(NTHREADS);                     // 128
    attn_corr_kernel<<<grid, block>>>(u, pan, Wphi, Wg, out);
}

// round 3
// speedup vs baseline: 1.9663x; 1.0798x over previous
#include <cuda_runtime.h>
#include <cuda_bf16.h>

// Problem constants (fixed by the dataset: b=2, c=8, h=w=128, P=3, Wn=7)
#define IMG_H 128
#define IMG_W 128
#define NCH 8
#define NB 2

#define TY 8
#define TX 16
#define NTHREADS (TY*TX)
#define HP 4                 // phi halo: window +-3 plus patch +-1
#define HG 3                 // g halo: window +-3
#define PH (TY + 2*HP)       // 16
#define PW (TX + 2*HP)       // 24
#define GH (TY + 2*HG)       // 14
#define GW (TX + 2*HG)       // 22

// Correlation map: tile dilated by 1 pixel (patch radius)
#define CW 18                // TX + 2
#define CHh 10               // TY + 2
#define CN (CHh*CW)          // 180

__global__ __launch_bounds__(NTHREADS)
void attn_corr_row_kernel(const float* __restrict__ u,
                          const float* __restrict__ pan,
                          const float* __restrict__ Wphi,
                          const float* __restrict__ Wg,
                          float* __restrict__ out)
{
    __shared__ __align__(16) float phi_s[PH*PW*NCH];
    __shared__ __align__(16) float g_s[GH*GW*NCH];
    __shared__ float Cs[2][7][CN];       // double-buffered row of 7 corr maps
    __shared__ float wphi_s[NCH*NCH];
    __shared__ float wg_s[NCH*NCH];

    const int tid  = threadIdx.x;
    const int bimg = blockIdx.z;
    const int y0   = blockIdx.y * TY;
    const int x0   = blockIdx.x * TX;

    if (tid < NCH*NCH) { wphi_s[tid] = Wphi[tid]; wg_s[tid] = Wg[tid]; }
    __syncthreads();

    const float* panb = pan + (size_t)bimg * NCH * IMG_H * IMG_W;
    const float* ub   = u   + (size_t)bimg * NCH * IMG_H * IMG_W;

    // ---- phi0 tile with +-4 halo: phi0 = W_phi @ pan (zero outside image) ----
    for (int i = tid; i < PH*PW; i += NTHREADS) {
        int r = i / PW, c = i % PW;
        int gy = y0 - HP + r, gx = x0 - HP + c;
        bool in = ((unsigned)gy < IMG_H) && ((unsigned)gx < IMG_W);
        float pv[NCH];
        #pragma unroll
        for (int ch = 0; ch < NCH; ch++)
            pv[ch] = in ? panb[ch*IMG_H*IMG_W + gy*IMG_W + gx] : 0.f;
        #pragma unroll
        for (int o = 0; o < NCH; o++) {
            float acc = 0.f;
            #pragma unroll
            for (int ci = 0; ci < NCH; ci++)
                acc = fmaf(wphi_s[o*NCH+ci], pv[ci], acc);
            phi_s[i*NCH + o] = acc;
        }
    }

    // ---- g tile with +-3 halo: g = W_g @ u (zero outside image) ----
    for (int i = tid; i < GH*GW; i += NTHREADS) {
        int r = i / GW, c = i % GW;
        int gy = y0 - HG + r, gx = x0 - HG + c;
        bool in = ((unsigned)gy < IMG_H) && ((unsigned)gx < IMG_W);
        float uv[NCH];
        #pragma unroll
        for (int ch = 0; ch < NCH; ch++)
            uv[ch] = in ? ub[ch*IMG_H*IMG_W + gy*IMG_W + gx] : 0.f;
        #pragma unroll
        for (int o = 0; o < NCH; o++) {
            float acc = 0.f;
            #pragma unroll
            for (int ci = 0; ci < NCH; ci++)
                acc = fmaf(wg_s[o*NCH+ci], uv[ci], acc);
            g_s[i*NCH + o] = acc;
        }
    }
    __syncthreads();

    const int ty = tid / TX, tx = tid % TX;
    const int gy = y0 + ty, gx = x0 + tx;

    // ---- cache v(a) for this thread's correlation positions in registers ----
    const int p0   = tid;                     // 0..127
    const int r0   = p0 / CW, c0 = p0 % CW;
    const int cell0 = (r0 + 3) * PW + (c0 + 3);
    float4 v0a = *(const float4*)&phi_s[cell0*NCH];
    float4 v0b = *(const float4*)&phi_s[cell0*NCH + 4];

    const bool has1 = (tid < CN - NTHREADS);  // tid < 52
    const int p1   = tid + NTHREADS;
    const int r1   = p1 / CW, c1 = p1 % CW;
    const int cell1 = (r1 + 3) * PW + (c1 + 3);
    float4 v1a = make_float4(0,0,0,0), v1b = make_float4(0,0,0,0);
    if (has1) {
        v1a = *(const float4*)&phi_s[cell1*NCH];
        v1b = *(const float4*)&phi_s[cell1*NCH + 4];
    }

    // ---- online softmax, one rescale per window ROW (7 dy iterations) ----
    float m = -3.4e38f, ssum = 0.f;
    float o0x=0.f,o0y=0.f,o0z=0.f,o0w=0.f;
    float o1x=0.f,o1y=0.f,o1z=0.f,o1w=0.f;

    #pragma unroll
    for (int dyi = 0; dyi < 7; dyi++) {
        const int dy = dyi - 3;
        float (*Cb)[CN] = Cs[dyi & 1];

        // --- produce C_{dy,dx} for all 7 dx (independent FMA chains) ---
        #pragma unroll
        for (int dxi = 0; dxi < 7; dxi++) {
            const int off = (dy * PW + (dxi - 3)) * NCH;
            const float4* q = (const float4*)&phi_s[cell0*NCH + off];
            float4 wa = q[0], wb = q[1];
            float cv = v0a.x*wa.x;
            cv = fmaf(v0a.y, wa.y, cv); cv = fmaf(v0a.z, wa.z, cv);
            cv = fmaf(v0a.w, wa.w, cv); cv = fmaf(v0b.x, wb.x, cv);
            cv = fmaf(v0b.y, wb.y, cv); cv = fmaf(v0b.z, wb.z, cv);
            cv = fmaf(v0b.w, wb.w, cv);
            Cb[dxi][p0] = cv;
        }
        if (has1) {
            #pragma unroll
            for (int dxi = 0; dxi < 7; dxi++) {
                const int off = (dy * PW + (dxi - 3)) * NCH;
                const float4* q = (const float4*)&phi_s[cell1*NCH + off];
                float4 wa = q[0], wb = q[1];
                float cv = v1a.x*wa.x;
                cv = fmaf(v1a.y, wa.y, cv); cv = fmaf(v1a.z, wa.z, cv);
                cv = fmaf(v1a.w, wa.w, cv); cv = fmaf(v1b.x, wb.x, cv);
                cv = fmaf(v1b.y, wb.y, cv); cv = fmaf(v1b.z, wb.z, cv);
                cv = fmaf(v1b.w, wb.w, cv);
                Cb[dxi][p1] = cv;
            }
        }
        __syncthreads();

        // --- 7 logits via 3x3 box-sums (independent address streams) ---
        const bool in_y = ((unsigned)(gy + dy) < IMG_H);
        float l[7];
        #pragma unroll
        for (int dxi = 0; dxi < 7; dxi++) {
            const float* base = &Cb[dxi][ty * CW + tx];
            float v = base[0]      + base[1]      + base[2]
                    + base[CW]     + base[CW+1]   + base[CW+2]
                    + base[2*CW]   + base[2*CW+1] + base[2*CW+2];
            const bool in = in_y && ((unsigned)(gx + dxi - 3) < IMG_W);
            l[dxi] = in ? v : 0.f;
        }

        // --- one rescale for the whole row, then 7 independent accumulations ---
        float mrow = fmaxf(fmaxf(fmaxf(l[0], l[1]), fmaxf(l[2], l[3])),
                           fmaxf(fmaxf(l[4], l[5]), l[6]));
        float mn = fmaxf(m, mrow);
        float sc = __expf(m - mn);     // first row: exp(-huge) -> 0
        ssum *= sc;
        o0x *= sc; o0y *= sc; o0z *= sc; o0w *= sc;
        o1x *= sc; o1y *= sc; o1z *= sc; o1w *= sc;

        const int girow = (ty + HG + dy) * GW + tx;   // dx=-3 start (tx+HG-3)
        #pragma unroll
        for (int dxi = 0; dxi < 7; dxi++) {
            float e = __expf(l[dxi] - mn);
            const int gi = (girow + dxi) * NCH;
            float4 gv0 = *(const float4*)&g_s[gi];
            float4 gv1 = *(const float4*)&g_s[gi + 4];
            ssum += e;
            o0x = fmaf(e, gv0.x, o0x);  o0y = fmaf(e, gv0.y, o0y);
            o0z = fmaf(e, gv0.z, o0z);  o0w = fmaf(e, gv0.w, o0w);
            o1x = fmaf(e, gv1.x, o1x);  o1y = fmaf(e, gv1.y, o1y);
            o1z = fmaf(e, gv1.z, o1z);  o1w = fmaf(e, gv1.w, o1w);
        }
        m = mn;
    }

    float inv = 1.f / ssum;
    float* ob = out + (size_t)bimg*NCH*IMG_H*IMG_W + (size_t)gy*IMG_W + gx;
    const int PL = IMG_H*IMG_W;
    ob[0*PL] = o0x*inv;  ob[1*PL] = o0y*inv;
    ob[2*PL] = o0z*inv;  ob[3*PL] = o0w*inv;
    ob[4*PL] = o1x*inv;  ob[5*PL] = o1y*inv;
    ob[6*PL] = o1z*inv;  ob[7*PL] = o1w*inv;
}

extern "C" void kernel_launch(void* const* d_in, const int* in_sizes, int n_in,
                              void* d_out, int out_size)
{
    const float* u    = (const float*)d_in[0];
    const float* pan  = (const float*)d_in[1];
    const float* Wphi = (const float*)d_in[2];
    const float* Wg   = (const float*)d_in[3];
    float* out = (float*)d_out;

    dim3 grid(IMG_W / TX, IMG_H / TY, NB);   // (8, 16, 2) = 256 blocks
    dim3 block(NTHREADS);                     // 128
    attn_corr_row_kernel<<<grid, block>>>(u, pan, Wphi, Wg, out);
}

// round 4
// speedup vs baseline: 2.4607x; 1.2514x over previous
#include <cuda_runtime.h>
#include <cuda_bf16.h>

// Problem constants (fixed by the dataset: b=2, c=8, h=w=128, P=3, Wn=7)
#define IMG_H 128
#define IMG_W 128
#define NCH 8
#define NB 2
#define PL (IMG_H*IMG_W)

#define TY 8
#define TX 16
#define NPIX (TY*TX)          // 128 pixels per tile
#define NSLICE 4
#define NTHREADS (NPIX*NSLICE) // 512
#define HP 4                  // phi halo: window +-3 plus patch +-1
#define HG 3                  // g halo: window +-3
#define PH (TY + 2*HP)        // 16
#define PW (TX + 2*HP)        // 24
#define GH (TY + 2*HG)        // 14
#define GW (TX + 2*HG)        // 22

// Correlation map: tile dilated by 1 pixel (patch radius)
#define CW 18                 // TX + 2
#define CHh 10                // TY + 2
#define CN (CHh*CW)           // 180 logical positions
#define CNP 184               // padded stride (also makes Cs big enough for merge)

__global__ __launch_bounds__(NTHREADS, 2)
void attn_slice_kernel(const float* __restrict__ u,
                       const float* __restrict__ pan,
                       const float* __restrict__ Wphi,
                       const float* __restrict__ Wg,
                       float* __restrict__ out)
{
    // channel-plane layout: conflict-free 16B-stride LDS.128
    __shared__ __align__(16) float4 phiA[PH*PW], phiB[PH*PW];
    __shared__ __align__(16) float4 gA[GH*GW],  gB[GH*GW];
    __shared__ float Cs[NSLICE][7][CNP];        // per-slice row of 7 corr maps
    __shared__ float wphi_s[NCH*NCH];
    __shared__ float wg_s[NCH*NCH];

    const int tid  = threadIdx.x;
    const int bimg = blockIdx.z;
    const int y0   = blockIdx.y * TY;
    const int x0   = blockIdx.x * TX;

    if (tid < NCH*NCH)                wphi_s[tid] = Wphi[tid];
    else if (tid < 2*NCH*NCH)         wg_s[tid - NCH*NCH] = Wg[tid - NCH*NCH];
    __syncthreads();

    const float* panb = pan + (size_t)bimg * NCH * PL;
    const float* ub   = u   + (size_t)bimg * NCH * PL;

    // ---- phi0 tile with +-4 halo: phi0 = W_phi @ pan (zero outside image) ----
    for (int i = tid; i < PH*PW; i += NTHREADS) {
        int r = i / PW, c = i % PW;
        int yy = y0 - HP + r, xx = x0 - HP + c;
        bool in = ((unsigned)yy < IMG_H) && ((unsigned)xx < IMG_W);
        float pv[NCH];
        #pragma unroll
        for (int ch = 0; ch < NCH; ch++)
            pv[ch] = in ? panb[ch*PL + yy*IMG_W + xx] : 0.f;
        float po[NCH];
        #pragma unroll
        for (int o = 0; o < NCH; o++) {
            float acc = 0.f;
            #pragma unroll
            for (int ci = 0; ci < NCH; ci++)
                acc = fmaf(wphi_s[o*NCH+ci], pv[ci], acc);
            po[o] = acc;
        }
        phiA[i] = make_float4(po[0], po[1], po[2], po[3]);
        phiB[i] = make_float4(po[4], po[5], po[6], po[7]);
    }

    // ---- g tile with +-3 halo: g = W_g @ u (zero outside image) ----
    for (int i = tid; i < GH*GW; i += NTHREADS) {
        int r = i / GW, c = i % GW;
        int yy = y0 - HG + r, xx = x0 - HG + c;
        bool in = ((unsigned)yy < IMG_H) && ((unsigned)xx < IMG_W);
        float uv[NCH];
        #pragma unroll
        for (int ch = 0; ch < NCH; ch++)
            uv[ch] = in ? ub[ch*PL + yy*IMG_W + xx] : 0.f;
        float go[NCH];
        #pragma unroll
        for (int o = 0; o < NCH; o++) {
            float acc = 0.f;
            #pragma unroll
            for (int ci = 0; ci < NCH; ci++)
                acc = fmaf(wg_s[o*NCH+ci], uv[ci], acc);
            go[o] = acc;
        }
        gA[i] = make_float4(go[0], go[1], go[2], go[3]);
        gB[i] = make_float4(go[4], go[5], go[6], go[7]);
    }
    __syncthreads();

    const int px    = tid & (NPIX-1);      // pixel within tile
    const int slice = tid >> 7;            // 0..3
    const int ty = px / TX, tx = px % TX;
    const int gy = y0 + ty, gx = x0 + tx;

    // correlation positions handled by this thread (within its slice)
    const int p0    = px;                            // 0..127
    const int cell0 = (p0/CW + 3) * PW + (p0%CW + 3);
    const float4 v0a = phiA[cell0];
    const float4 v0b = phiB[cell0];
    const bool has1 = (px < CN - NPIX);              // px < 52
    const int p1    = px + NPIX;
    const int cell1 = (p1/CW + 3) * PW + (p1%CW + 3);
    float4 v1a = make_float4(0,0,0,0), v1b = make_float4(0,0,0,0);
    if (has1) { v1a = phiA[cell1]; v1b = phiB[cell1]; }

    // partial online softmax over this slice's dy rows
    float m = -3.4e38f, ssum = 0.f;
    float o0x=0.f,o0y=0.f,o0z=0.f,o0w=0.f;
    float o1x=0.f,o1y=0.f,o1z=0.f,o1w=0.f;

    #pragma unroll
    for (int rnd = 0; rnd < 2; rnd++) {
        const int dyi = rnd * NSLICE + slice;   // 0..7
        const bool active = (dyi < 7);
        const int dy = dyi - 3;

        if (active) {
            // produce 7 correlation maps C_{dy,dx} for this slice
            #pragma unroll
            for (int dxi = 0; dxi < 7; dxi++) {
                const int off = dy * PW + (dxi - 3);
                {
                    float4 wa = phiA[cell0 + off], wb = phiB[cell0 + off];
                    float cv = v0a.x*wa.x;
                    cv = fmaf(v0a.y, wa.y, cv); cv = fmaf(v0a.z, wa.z, cv);
                    cv = fmaf(v0a.w, wa.w, cv); cv = fmaf(v0b.x, wb.x, cv);
                    cv = fmaf(v0b.y, wb.y, cv); cv = fmaf(v0b.z, wb.z, cv);
                    cv = fmaf(v0b.w, wb.w, cv);
                    Cs[slice][dxi][p0] = cv;
                }
                if (has1) {
                    float4 wa = phiA[cell1 + off], wb = phiB[cell1 + off];
                    float cv = v1a.x*wa.x;
                    cv = fmaf(v1a.y, wa.y, cv); cv = fmaf(v1a.z, wa.z, cv);
                    cv = fmaf(v1a.w, wa.w, cv); cv = fmaf(v1b.x, wb.x, cv);
                    cv = fmaf(v1b.y, wb.y, cv); cv = fmaf(v1b.z, wb.z, cv);
                    cv = fmaf(v1b.w, wb.w, cv);
                    Cs[slice][dxi][p1] = cv;
                }
            }
        }
        __syncthreads();

        if (active) {
            const bool in_y = ((unsigned)(gy + dy) < IMG_H);
            float l[7];
            #pragma unroll
            for (int dxi = 0; dxi < 7; dxi++) {
                const float* base = &Cs[slice][dxi][ty * CW + tx];
                float v = base[0]      + base[1]      + base[2]
                        + base[CW]     + base[CW+1]   + base[CW+2]
                        + base[2*CW]   + base[2*CW+1] + base[2*CW+2];
                const bool in = in_y && ((unsigned)(gx + dxi - 3) < IMG_W);
                l[dxi] = in ? v : 0.f;
            }
            float mrow = fmaxf(fmaxf(fmaxf(l[0], l[1]), fmaxf(l[2], l[3])),
                               fmaxf(fmaxf(l[4], l[5]), l[6]));
            float mn = fmaxf(m, mrow);
            float sc = __expf(m - mn);
            ssum *= sc;
            o0x *= sc; o0y *= sc; o0z *= sc; o0w *= sc;
            o1x *= sc; o1y *= sc; o1z *= sc; o1w *= sc;

            const int girow = (ty + HG + dy) * GW + tx;   // dxi adds 0..6
            #pragma unroll
            for (int dxi = 0; dxi < 7; dxi++) {
                float e = __expf(l[dxi] - mn);
                float4 gv0 = gA[girow + dxi];
                float4 gv1 = gB[girow + dxi];
                ssum += e;
                o0x = fmaf(e, gv0.x, o0x);  o0y = fmaf(e, gv0.y, o0y);
                o0z = fmaf(e, gv0.z, o0z);  o0w = fmaf(e, gv0.w, o0w);
                o1x = fmaf(e, gv1.x, o1x);  o1y = fmaf(e, gv1.y, o1y);
                o1z = fmaf(e, gv1.z, o1z);  o1w = fmaf(e, gv1.w, o1w);
            }
            m = mn;
        }
        if (rnd == 0) __syncthreads();   // protect Cs before round-1 produce
    }

    // ---- merge 4 per-slice partial softmaxes (reuse Cs as scratch) ----
    __syncthreads();                      // everyone done reading Cs
    float* red = &Cs[0][0][0];            // 4*7*184 = 5152 >= 10*512 floats
    red[tid]            = m;
    red[NTHREADS + tid] = ssum;
    red[2*NTHREADS + 0*NTHREADS + tid] = o0x;
    red[2*NTHREADS + 1*NTHREADS + tid] = o0y;
    red[2*NTHREADS + 2*NTHREADS + tid] = o0z;
    red[2*NTHREADS + 3*NTHREADS + tid] = o0w;
    red[2*NTHREADS + 4*NTHREADS + tid] = o1x;
    red[2*NTHREADS + 5*NTHREADS + tid] = o1y;
    red[2*NTHREADS + 6*NTHREADS + tid] = o1z;
    red[2*NTHREADS + 7*NTHREADS + tid] = o1w;
    __syncthreads();

    if (slice == 0) {
        float mm[NSLICE];
        #pragma unroll
        for (int s = 0; s < NSLICE; s++) mm[s] = red[s*NPIX + px];
        float M = fmaxf(fmaxf(mm[0], mm[1]), fmaxf(mm[2], mm[3]));

        float S = 0.f;
        float oo[NCH];
        #pragma unroll
        for (int ch = 0; ch < NCH; ch++) oo[ch] = 0.f;
        #pragma unroll
        for (int s = 0; s < NSLICE; s++) {
            float w = __expf(mm[s] - M);
            S = fmaf(red[NTHREADS + s*NPIX + px], w, S);
            #pragma unroll
            for (int ch = 0; ch < NCH; ch++)
                oo[ch] = fmaf(red[2*NTHREADS + ch*NTHREADS + s*NPIX + px], w, oo[ch]);
        }
        float inv = 1.f / S;
        float* ob = out + (size_t)bimg*NCH*PL + (size_t)gy*IMG_W + gx;
        #pragma unroll
        for (int ch = 0; ch < NCH; ch++)
            ob[ch*PL] = oo[ch] * inv;
    }
}

extern "C" void kernel_launch(void* const* d_in, const int* in_sizes, int n_in,
                              void* d_out, int out_size)
{
    const float* u    = (const float*)d_in[0];
    const float* pan  = (const float*)d_in[1];
    const float* Wphi = (const float*)d_in[2];
    const float* Wg   = (const float*)d_in[3];
    float* out = (float*)d_out;

    dim3 grid(IMG_W / TX, IMG_H / TY, NB);   // (8, 16, 2) = 256 blocks
    dim3 block(NTHREADS);                     // 512
    attn_slice_kernel<<<grid, block>>>(u, pan, Wphi, Wg, out);
}